// round 9
// baseline (speedup 1.0000x reference)
#include <cuda_runtime.h>
#include <cuda_fp16.h>
#include <math.h>

#define MAX_NODES 50000
#define MAX_EDGES 1500000
#define FEAT 128
#define SCAN_BLK 256
#define MAX_SCAN_BLOCKS 256   // ceil(50000/256)=196

// Scratch (device globals; allocation-free rule)
__device__ float  g_agg[MAX_NODES * FEAT];
__device__ __half g_xh[MAX_NODES * FEAT];     // fp16 copy of x
__device__ int    g_deg[MAX_NODES];
__device__ int    g_rowstart[MAX_NODES];
__device__ int    g_writeptr[MAX_NODES];
__device__ int    g_blocksum[MAX_SCAN_BLOCKS];
__device__ uint2  g_rec[MAX_EDGES];           // {sender, weight-bits}

// ---------------------------------------------------------------------------
// 0) prep: convert x -> fp16 AND zero degree counters (one launch)
// ---------------------------------------------------------------------------
__global__ void prep_kernel(const float* __restrict__ x,
                            __half* __restrict__ xh,
                            int* __restrict__ deg, int n8, int n_nodes) {
    int i = blockIdx.x * blockDim.x + threadIdx.x;
    if (i < n_nodes) deg[i] = 0;
    if (i >= n8) return;
    const float4* x4 = (const float4*)x;
    float4 a = x4[2 * i];
    float4 b = x4[2 * i + 1];
    __half2 h0 = __floats2half2_rn(a.x, a.y);
    __half2 h1 = __floats2half2_rn(a.z, a.w);
    __half2 h2 = __floats2half2_rn(b.x, b.y);
    __half2 h3 = __floats2half2_rn(b.z, b.w);
    uint4 o;
    o.x = *(unsigned*)&h0; o.y = *(unsigned*)&h1;
    o.z = *(unsigned*)&h2; o.w = *(unsigned*)&h3;
    ((uint4*)xh)[i] = o;
}

// ---------------------------------------------------------------------------
// 2) histogram of receivers
// ---------------------------------------------------------------------------
__global__ void hist_kernel(const int* __restrict__ ei, int* __restrict__ deg,
                            int E, int n_nodes) {
    int e = blockIdx.x * blockDim.x + threadIdx.x;
    if (e >= E) return;
    int r = ei[E + e];
    r = min(max(r, 0), n_nodes - 1);
    atomicAdd(deg + r, 1);           // no return use -> REDG
}

// ---------------------------------------------------------------------------
// 3) decoupled scan (all shfls with full-warp activity)
// ---------------------------------------------------------------------------
__device__ __forceinline__ int warp_incl_scan(int v, int lane) {
#pragma unroll
    for (int off = 1; off < 32; off <<= 1) {
        int u = __shfl_up_sync(0xffffffffu, v, off);
        if (lane >= off) v += u;
    }
    return v;
}

__global__ void scan_reduce_kernel(const int* __restrict__ deg,
                                   int* __restrict__ blocksum, int n) {
    __shared__ int warpsum[SCAN_BLK / 32];
    int t = threadIdx.x;
    int idx = blockIdx.x * SCAN_BLK + t;
    int v = (idx < n) ? deg[idx] : 0;
#pragma unroll
    for (int off = 16; off > 0; off >>= 1)
        v += __shfl_down_sync(0xffffffffu, v, off);
    if ((t & 31) == 0) warpsum[t >> 5] = v;
    __syncthreads();
    if (t < 32) {
        int s = (t < SCAN_BLK / 32) ? warpsum[t] : 0;
#pragma unroll
        for (int off = 16; off > 0; off >>= 1)
            s += __shfl_down_sync(0xffffffffu, s, off);
        if (t == 0) blocksum[blockIdx.x] = s;
    }
}

__global__ void scan_top_kernel(int* __restrict__ blocksum, int nb) {
    __shared__ int sh[SCAN_BLK / 32];
    int t = threadIdx.x;
    int lane = t & 31;
    int w = t >> 5;
    int v = (t < nb) ? blocksum[t] : 0;
    int incl = warp_incl_scan(v, lane);
    if (lane == 31) sh[w] = incl;
    __syncthreads();
    if (t < 32) {
        int s = (t < SCAN_BLK / 32) ? sh[t] : 0;
        int si = warp_incl_scan(s, t);
        if (t < SCAN_BLK / 32) sh[t] = si - s;
    }
    __syncthreads();
    if (t < nb) blocksum[t] = incl - v + sh[w];
}

__global__ void scan_final_kernel(const int* __restrict__ deg,
                                  const int* __restrict__ blocksum,
                                  int* __restrict__ rowstart,
                                  int* __restrict__ writeptr, int n) {
    __shared__ int sh[SCAN_BLK / 32];
    int t = threadIdx.x;
    int lane = t & 31;
    int w = t >> 5;
    int idx = blockIdx.x * SCAN_BLK + t;
    int v = (idx < n) ? deg[idx] : 0;
    int incl = warp_incl_scan(v, lane);
    if (lane == 31) sh[w] = incl;
    __syncthreads();
    if (t < 32) {
        int s = (t < SCAN_BLK / 32) ? sh[t] : 0;
        int si = warp_incl_scan(s, t);
        if (t < SCAN_BLK / 32) sh[t] = si - s;
    }
    __syncthreads();
    if (idx < n) {
        int start = blocksum[blockIdx.x] + sh[w] + incl - v;
        rowstart[idx] = start;
        writeptr[idx] = start;
    }
}

// ---------------------------------------------------------------------------
// 4) scatter: 4 edges/thread (e = t, t+T, t+2T, t+3T), 4 in-flight atomics.
//    Threads with t >= T exit: their edges belong to threads t-T etc.
// ---------------------------------------------------------------------------
__global__ void scatter_kernel(const int* __restrict__ ei,
                               const float* __restrict__ elen,
                               const float* __restrict__ log_scale_p,
                               const float* __restrict__ fw_p,
                               const float* __restrict__ fb_p,
                               int* __restrict__ writeptr,
                               uint2* __restrict__ rec,
                               int E, int n_nodes, int T) {
    int t = blockIdx.x * blockDim.x + threadIdx.x;
    if (t >= T) return;   // critical: avoid double-processing edges
    float scale = expf(log_scale_p[0]);
    float inv_s = 1.f / (scale + 1e-6f);
    float fw = fw_p[0];
    float fb = fb_p[0];

    int   s[4], r[4];
    float len[4];
    bool  ok[4];
#pragma unroll
    for (int u = 0; u < 4; u++) {
        int e = t + u * T;
        ok[u] = (e < E);
        if (ok[u]) {
            s[u]   = ei[e];
            r[u]   = ei[E + e];
            len[u] = elen[e];
        }
    }
    float w[4];
    int   pos[4];
#pragma unroll
    for (int u = 0; u < 4; u++) {
        if (ok[u]) {
            s[u] = min(max(s[u], 0), n_nodes - 1);
            r[u] = min(max(r[u], 0), n_nodes - 1);
            float tt = fmaxf(len[u] * inv_s, 0.f);
            float d = expf(-tt * tt);
            float g = 1.f / (1.f + expf(-(len[u] * fw + fb)));
            float ww = d * g;
            if (!(ww > -3.0e38f && ww < 3.0e38f)) ww = 0.f;
            w[u] = ww;
        }
    }
#pragma unroll
    for (int u = 0; u < 4; u++) {
        if (ok[u]) pos[u] = atomicAdd(writeptr + r[u], 1);
    }
#pragma unroll
    for (int u = 0; u < 4; u++) {
        if (ok[u]) rec[pos[u]] = make_uint2((unsigned)s[u],
                                            __float_as_uint(w[u]));
    }
}

// ---------------------------------------------------------------------------
// 5) gather (fp16 x): warp per node, uniform 8-wide blocks (no serial tail).
//    Lanes >= n hold {s=0, w=0}: harmless cached row-0 loads.
// ---------------------------------------------------------------------------
__global__ void gather_kernel(const __half* __restrict__ xh,
                              const uint2* __restrict__ rec,
                              const int* __restrict__ rowstart,
                              const int* __restrict__ deg,
                              float* __restrict__ agg, int n_nodes) {
    int wid  = (blockIdx.x * blockDim.x + threadIdx.x) >> 5;
    int lane = threadIdx.x & 31;
    if (wid >= n_nodes) return;

    int base = rowstart[wid];
    int d    = deg[wid];
    float4 acc = make_float4(0.f, 0.f, 0.f, 0.f);

    for (int j0 = 0; j0 < d; j0 += 32) {
        int n = min(32, d - j0);
        uint2 rv = make_uint2(0u, 0u);
        if (lane < n) rv = rec[base + j0 + lane];

        for (int k = 0; k < n; k += 8) {
            int   si[8];
            float wi[8];
#pragma unroll
            for (int u = 0; u < 8; u++) {
                si[u] = __shfl_sync(0xffffffffu, (int)rv.x, k + u);
                wi[u] = __uint_as_float(__shfl_sync(0xffffffffu, rv.y, k + u));
            }
            uint2 hv[8];
#pragma unroll
            for (int u = 0; u < 8; u++) {
                hv[u] = ((const uint2*)(xh + (size_t)si[u] * FEAT))[lane];
            }
#pragma unroll
            for (int u = 0; u < 8; u++) {
                float2 f0 = __half22float2(*(__half2*)&hv[u].x);
                float2 f1 = __half22float2(*(__half2*)&hv[u].y);
                acc.x = fmaf(wi[u], f0.x, acc.x);
                acc.y = fmaf(wi[u], f0.y, acc.y);
                acc.z = fmaf(wi[u], f1.x, acc.z);
                acc.w = fmaf(wi[u], f1.y, acc.w);
            }
        }
    }

    float inv = 1.f / fmaxf((float)d, 1.f);
    ((float4*)(agg + (size_t)wid * FEAT))[lane] =
        make_float4(acc.x * inv, acc.y * inv, acc.z * inv, acc.w * inv);
}

// ---------------------------------------------------------------------------
// 6) out = x + agg @ W_mix — FFMA2 inner loop with pre-duplicated f32x2 A tile
// ---------------------------------------------------------------------------
#define BM 64

__global__ void gemm_kernel(const float* __restrict__ x,
                            const float* __restrict__ W,
                            const float* __restrict__ agg,
                            float* __restrict__ out,
                            int n_nodes) {
    extern __shared__ float sm[];
    float*  Ws  = sm;                             // 128*128 f32 (64 KB)
    float2* As2 = (float2*)(sm + FEAT * FEAT);    // BM*128 f32x2 dup (64 KB)

    int tid = threadIdx.x;
    int row0 = blockIdx.x * BM;

    for (int i = tid; i < FEAT * FEAT / 4; i += 256) {
        ((float4*)Ws)[i] = ((const float4*)W)[i];
    }
    for (int i = tid; i < BM * FEAT / 4; i += 256) {
        int r = i / (FEAT / 4);
        int c = i % (FEAT / 4);
        int row = row0 + r;
        float4 v = make_float4(0.f, 0.f, 0.f, 0.f);
        if (row < n_nodes) {
            v = ((const float4*)(agg + (size_t)row * FEAT))[c];
        }
        float2* dst = As2 + r * FEAT + c * 4;
        dst[0] = make_float2(v.x, v.x);
        dst[1] = make_float2(v.y, v.y);
        dst[2] = make_float2(v.z, v.z);
        dst[3] = make_float2(v.w, v.w);
    }
    __syncthreads();

    int tx = tid & 31;   // cols [tx*4, tx*4+3]
    int ty = tid >> 5;   // rows [ty*8, ty*8+7]

    unsigned long long acc01[8], acc23[8];
#pragma unroll
    for (int r = 0; r < 8; r++) { acc01[r] = 0ull; acc23[r] = 0ull; }

#pragma unroll 4
    for (int k = 0; k < FEAT; k++) {
        ulonglong2 w2 = *(const ulonglong2*)(Ws + k * FEAT + tx * 4);
#pragma unroll
        for (int r = 0; r < 8; r++) {
            unsigned long long aa =
                *(const unsigned long long*)(As2 + (ty * 8 + r) * FEAT + k);
            asm("fma.rn.f32x2 %0, %1, %2, %0;" : "+l"(acc01[r]) : "l"(aa), "l"(w2.x));
            asm("fma.rn.f32x2 %0, %1, %2, %0;" : "+l"(acc23[r]) : "l"(aa), "l"(w2.y));
        }
    }

#pragma unroll
    for (int r = 0; r < 8; r++) {
        int row = row0 + ty * 8 + r;
        if (row < n_nodes) {
            unsigned c0u, c1u, c2u, c3u;
            asm("mov.b64 {%0, %1}, %2;" : "=r"(c0u), "=r"(c1u) : "l"(acc01[r]));
            asm("mov.b64 {%0, %1}, %2;" : "=r"(c2u), "=r"(c3u) : "l"(acc23[r]));
            float4 xv = ((const float4*)(x + (size_t)row * FEAT))[tx];
            float4 o = make_float4(__uint_as_float(c0u) + xv.x,
                                   __uint_as_float(c1u) + xv.y,
                                   __uint_as_float(c2u) + xv.z,
                                   __uint_as_float(c3u) + xv.w);
            ((float4*)(out + (size_t)row * FEAT))[tx] = o;
        }
    }
}

// ---------------------------------------------------------------------------
extern "C" void kernel_launch(void* const* d_in, const int* in_sizes, int n_in,
                              void* d_out, int out_size) {
    const float* x    = (const float*)d_in[0];
    const int*   ei   = (const int*)d_in[1];
    const float* elen = (const float*)d_in[2];
    const float* W    = (const float*)d_in[3];
    const float* lsc  = (const float*)d_in[4];
    const float* fw   = (const float*)d_in[5];
    const float* fb   = (const float*)d_in[6];
    float* out = (float*)d_out;

    int n_nodes = in_sizes[0] / FEAT;
    int E       = in_sizes[2];
    if (E > MAX_EDGES) E = MAX_EDGES;

    float*  agg;      cudaGetSymbolAddress((void**)&agg, g_agg);
    __half* xh;       cudaGetSymbolAddress((void**)&xh, g_xh);
    int*    deg;      cudaGetSymbolAddress((void**)&deg, g_deg);
    int*    rowstart; cudaGetSymbolAddress((void**)&rowstart, g_rowstart);
    int*    writeptr; cudaGetSymbolAddress((void**)&writeptr, g_writeptr);
    int*    blocksum; cudaGetSymbolAddress((void**)&blocksum, g_blocksum);
    uint2*  rec;      cudaGetSymbolAddress((void**)&rec, g_rec);

    // 0+1) convert x -> fp16 and zero degree counters
    {
        int n8 = n_nodes * FEAT / 8;
        prep_kernel<<<(n8 + 255) / 256, 256>>>(x, xh, deg, n8, n_nodes);
    }

    // 2) receiver histogram
    hist_kernel<<<(E + 255) / 256, 256>>>(ei, deg, E, n_nodes);

    // 3) decoupled prefix scan -> rowstart / writeptr
    {
        int nb = (n_nodes + SCAN_BLK - 1) / SCAN_BLK;   // 196
        scan_reduce_kernel<<<nb, SCAN_BLK>>>(deg, blocksum, n_nodes);
        scan_top_kernel<<<1, SCAN_BLK>>>(blocksum, nb);
        scan_final_kernel<<<nb, SCAN_BLK>>>(deg, blocksum, rowstart,
                                            writeptr, n_nodes);
    }

    // 4) bucket scatter, 4 edges per thread
    {
        int T = (E + 3) / 4;
        scatter_kernel<<<(T + 255) / 256, 256>>>(ei, elen, lsc, fw, fb,
                                                 writeptr, rec, E, n_nodes, T);
    }

    // 5) race-free per-node gather (warp per node)
    {
        long long total = (long long)n_nodes * 32;
        int blocks = (int)((total + 255) / 256);
        gather_kernel<<<blocks, 256>>>(xh, rec, rowstart, deg, agg, n_nodes);
    }

    // 6) GEMM + residual
    {
        int smem = (FEAT * FEAT + 2 * BM * FEAT) * (int)sizeof(float); // 128 KB
        cudaFuncSetAttribute(gemm_kernel,
                             cudaFuncAttributeMaxDynamicSharedMemorySize, smem);
        gemm_kernel<<<(n_nodes + BM - 1) / BM, 256, smem>>>(x, W, agg, out,
                                                            n_nodes);
    }
}

// round 10
// speedup vs baseline: 1.2806x; 1.2806x over previous
#include <cuda_runtime.h>
#include <cuda_fp16.h>
#include <math.h>

#define MAX_NODES 50000
#define MAX_EDGES 1500000
#define FEAT 128
#define SCAN_BLK 256
#define MAX_SCAN_BLOCKS 256   // ceil(50000/256)=196

// Scratch (device globals; allocation-free rule)
__device__ float  g_agg[MAX_NODES * FEAT];
__device__ __half g_xh[MAX_NODES * FEAT];     // fp16 copy of x
__device__ int    g_deg[MAX_NODES];
__device__ int    g_rowstart[MAX_NODES];
__device__ int    g_writeptr[MAX_NODES];
__device__ int    g_blocksum[MAX_SCAN_BLOCKS];
__device__ uint2  g_rec[MAX_EDGES];           // {sender, weight-bits}

// ---------------------------------------------------------------------------
// 0) prep: convert x -> fp16 AND zero degree counters (one launch)
// ---------------------------------------------------------------------------
__global__ void prep_kernel(const float* __restrict__ x,
                            __half* __restrict__ xh,
                            int* __restrict__ deg, int n8, int n_nodes) {
    int i = blockIdx.x * blockDim.x + threadIdx.x;
    if (i < n_nodes) deg[i] = 0;
    if (i >= n8) return;
    const float4* x4 = (const float4*)x;
    float4 a = x4[2 * i];
    float4 b = x4[2 * i + 1];
    __half2 h0 = __floats2half2_rn(a.x, a.y);
    __half2 h1 = __floats2half2_rn(a.z, a.w);
    __half2 h2 = __floats2half2_rn(b.x, b.y);
    __half2 h3 = __floats2half2_rn(b.z, b.w);
    uint4 o;
    o.x = *(unsigned*)&h0; o.y = *(unsigned*)&h1;
    o.z = *(unsigned*)&h2; o.w = *(unsigned*)&h3;
    ((uint4*)xh)[i] = o;
}

// ---------------------------------------------------------------------------
// 2) histogram of receivers
// ---------------------------------------------------------------------------
__global__ void hist_kernel(const int* __restrict__ ei, int* __restrict__ deg,
                            int E, int n_nodes) {
    int e = blockIdx.x * blockDim.x + threadIdx.x;
    if (e >= E) return;
    int r = ei[E + e];
    r = min(max(r, 0), n_nodes - 1);
    atomicAdd(deg + r, 1);           // no return use -> REDG
}

// ---------------------------------------------------------------------------
// 3) decoupled scan (all shfls with full-warp activity)
// ---------------------------------------------------------------------------
__device__ __forceinline__ int warp_incl_scan(int v, int lane) {
#pragma unroll
    for (int off = 1; off < 32; off <<= 1) {
        int u = __shfl_up_sync(0xffffffffu, v, off);
        if (lane >= off) v += u;
    }
    return v;
}

__global__ void scan_reduce_kernel(const int* __restrict__ deg,
                                   int* __restrict__ blocksum, int n) {
    __shared__ int warpsum[SCAN_BLK / 32];
    int t = threadIdx.x;
    int idx = blockIdx.x * SCAN_BLK + t;
    int v = (idx < n) ? deg[idx] : 0;
#pragma unroll
    for (int off = 16; off > 0; off >>= 1)
        v += __shfl_down_sync(0xffffffffu, v, off);
    if ((t & 31) == 0) warpsum[t >> 5] = v;
    __syncthreads();
    if (t < 32) {
        int s = (t < SCAN_BLK / 32) ? warpsum[t] : 0;
#pragma unroll
        for (int off = 16; off > 0; off >>= 1)
            s += __shfl_down_sync(0xffffffffu, s, off);
        if (t == 0) blocksum[blockIdx.x] = s;
    }
}

__global__ void scan_top_kernel(int* __restrict__ blocksum, int nb) {
    __shared__ int sh[SCAN_BLK / 32];
    int t = threadIdx.x;
    int lane = t & 31;
    int w = t >> 5;
    int v = (t < nb) ? blocksum[t] : 0;
    int incl = warp_incl_scan(v, lane);
    if (lane == 31) sh[w] = incl;
    __syncthreads();
    if (t < 32) {
        int s = (t < SCAN_BLK / 32) ? sh[t] : 0;
        int si = warp_incl_scan(s, t);
        if (t < SCAN_BLK / 32) sh[t] = si - s;
    }
    __syncthreads();
    if (t < nb) blocksum[t] = incl - v + sh[w];
}

__global__ void scan_final_kernel(const int* __restrict__ deg,
                                  const int* __restrict__ blocksum,
                                  int* __restrict__ rowstart,
                                  int* __restrict__ writeptr, int n) {
    __shared__ int sh[SCAN_BLK / 32];
    int t = threadIdx.x;
    int lane = t & 31;
    int w = t >> 5;
    int idx = blockIdx.x * SCAN_BLK + t;
    int v = (idx < n) ? deg[idx] : 0;
    int incl = warp_incl_scan(v, lane);
    if (lane == 31) sh[w] = incl;
    __syncthreads();
    if (t < 32) {
        int s = (t < SCAN_BLK / 32) ? sh[t] : 0;
        int si = warp_incl_scan(s, t);
        if (t < SCAN_BLK / 32) sh[t] = si - s;
    }
    __syncthreads();
    if (idx < n) {
        int start = blocksum[blockIdx.x] + sh[w] + incl - v;
        rowstart[idx] = start;
        writeptr[idx] = start;
    }
}

// ---------------------------------------------------------------------------
// 4) scatter: thread t owns CONTIGUOUS edges 4t..4t+3 (disjoint by
//    construction). Vector loads (int4/float4) + 4 in-flight atomic returns.
// ---------------------------------------------------------------------------
__global__ void scatter_kernel(const int* __restrict__ ei,
                               const float* __restrict__ elen,
                               const float* __restrict__ log_scale_p,
                               const float* __restrict__ fw_p,
                               const float* __restrict__ fb_p,
                               int* __restrict__ writeptr,
                               uint2* __restrict__ rec,
                               int E, int n_nodes) {
    int t = blockIdx.x * blockDim.x + threadIdx.x;
    int e0 = t * 4;
    if (e0 >= E) return;

    float scale = expf(log_scale_p[0]);
    float inv_s = 1.f / (scale + 1e-6f);
    float fw = fw_p[0];
    float fb = fb_p[0];

    int   s[4], r[4];
    float len[4];
    int   cnt;
    if (e0 + 4 <= E && (E & 3) == 0) {
        // vector path: ei and ei+E both 16B-aligned at e0 (E % 4 == 0)
        int4   sv = *(const int4*)(ei + e0);
        int4   rv = *(const int4*)(ei + E + e0);
        float4 lv = *(const float4*)(elen + e0);
        s[0] = sv.x; s[1] = sv.y; s[2] = sv.z; s[3] = sv.w;
        r[0] = rv.x; r[1] = rv.y; r[2] = rv.z; r[3] = rv.w;
        len[0] = lv.x; len[1] = lv.y; len[2] = lv.z; len[3] = lv.w;
        cnt = 4;
    } else {
        cnt = min(4, E - e0);
        for (int u = 0; u < cnt; u++) {
            s[u]   = ei[e0 + u];
            r[u]   = ei[E + e0 + u];
            len[u] = elen[e0 + u];
        }
    }

    float w[4];
    int   pos[4];
#pragma unroll
    for (int u = 0; u < 4; u++) {
        if (u < cnt) {
            s[u] = min(max(s[u], 0), n_nodes - 1);
            r[u] = min(max(r[u], 0), n_nodes - 1);
            float tt = fmaxf(len[u] * inv_s, 0.f);
            float d = expf(-tt * tt);
            float g = 1.f / (1.f + expf(-(len[u] * fw + fb)));
            float ww = d * g;
            if (!(ww > -3.0e38f && ww < 3.0e38f)) ww = 0.f;
            w[u] = ww;
        }
    }
#pragma unroll
    for (int u = 0; u < 4; u++) {
        if (u < cnt) pos[u] = atomicAdd(writeptr + r[u], 1);
    }
#pragma unroll
    for (int u = 0; u < 4; u++) {
        if (u < cnt) rec[pos[u]] = make_uint2((unsigned)s[u],
                                              __float_as_uint(w[u]));
    }
}

// ---------------------------------------------------------------------------
// 5) gather (fp16 x): warp per node, uniform 8-wide blocks (no serial tail).
//    Lanes >= n hold {s=0, w=0}: harmless cached row-0 loads.
// ---------------------------------------------------------------------------
__global__ void gather_kernel(const __half* __restrict__ xh,
                              const uint2* __restrict__ rec,
                              const int* __restrict__ rowstart,
                              const int* __restrict__ deg,
                              float* __restrict__ agg, int n_nodes) {
    int wid  = (blockIdx.x * blockDim.x + threadIdx.x) >> 5;
    int lane = threadIdx.x & 31;
    if (wid >= n_nodes) return;

    int base = rowstart[wid];
    int d    = deg[wid];
    float4 acc = make_float4(0.f, 0.f, 0.f, 0.f);

    for (int j0 = 0; j0 < d; j0 += 32) {
        int n = min(32, d - j0);
        uint2 rv = make_uint2(0u, 0u);
        if (lane < n) rv = rec[base + j0 + lane];

        for (int k = 0; k < n; k += 8) {
            int   si[8];
            float wi[8];
#pragma unroll
            for (int u = 0; u < 8; u++) {
                si[u] = __shfl_sync(0xffffffffu, (int)rv.x, k + u);
                wi[u] = __uint_as_float(__shfl_sync(0xffffffffu, rv.y, k + u));
            }
            uint2 hv[8];
#pragma unroll
            for (int u = 0; u < 8; u++) {
                hv[u] = ((const uint2*)(xh + (size_t)si[u] * FEAT))[lane];
            }
#pragma unroll
            for (int u = 0; u < 8; u++) {
                float2 f0 = __half22float2(*(__half2*)&hv[u].x);
                float2 f1 = __half22float2(*(__half2*)&hv[u].y);
                acc.x = fmaf(wi[u], f0.x, acc.x);
                acc.y = fmaf(wi[u], f0.y, acc.y);
                acc.z = fmaf(wi[u], f1.x, acc.z);
                acc.w = fmaf(wi[u], f1.y, acc.w);
            }
        }
    }

    float inv = 1.f / fmaxf((float)d, 1.f);
    ((float4*)(agg + (size_t)wid * FEAT))[lane] =
        make_float4(acc.x * inv, acc.y * inv, acc.z * inv, acc.w * inv);
}

// ---------------------------------------------------------------------------
// 6) out = x + agg @ W_mix — FFMA2, in-register dup (96 KB smem, 2 CTA/SM)
// ---------------------------------------------------------------------------
#define BM 64

__global__ void gemm_kernel(const float* __restrict__ x,
                            const float* __restrict__ W,
                            const float* __restrict__ agg,
                            float* __restrict__ out,
                            int n_nodes) {
    extern __shared__ float sm[];
    float* Ws = sm;                  // 128*128
    float* As = sm + FEAT * FEAT;    // BM*128

    int tid = threadIdx.x;
    int row0 = blockIdx.x * BM;

    for (int i = tid; i < FEAT * FEAT / 4; i += 256) {
        ((float4*)Ws)[i] = ((const float4*)W)[i];
    }
    for (int i = tid; i < BM * FEAT / 4; i += 256) {
        int r = i / (FEAT / 4);
        int c = i % (FEAT / 4);
        int row = row0 + r;
        float4 v = make_float4(0.f, 0.f, 0.f, 0.f);
        if (row < n_nodes) {
            v = ((const float4*)(agg + (size_t)row * FEAT))[c];
        }
        ((float4*)(As + r * FEAT))[c] = v;
    }
    __syncthreads();

    int tx = tid & 31;   // cols [tx*4, tx*4+3]
    int ty = tid >> 5;   // rows [ty*8, ty*8+7]

    unsigned long long acc01[8], acc23[8];
#pragma unroll
    for (int r = 0; r < 8; r++) { acc01[r] = 0ull; acc23[r] = 0ull; }

#pragma unroll 4
    for (int k = 0; k < FEAT; k++) {
        ulonglong2 w2 = *(const ulonglong2*)(Ws + k * FEAT + tx * 4);
#pragma unroll
        for (int r = 0; r < 8; r++) {
            float a = As[(ty * 8 + r) * FEAT + k];   // warp-uniform broadcast
            unsigned long long aa;
            asm("mov.b64 %0, {%1, %1};" : "=l"(aa) : "r"(__float_as_uint(a)));
            asm("fma.rn.f32x2 %0, %1, %2, %0;" : "+l"(acc01[r]) : "l"(aa), "l"(w2.x));
            asm("fma.rn.f32x2 %0, %1, %2, %0;" : "+l"(acc23[r]) : "l"(aa), "l"(w2.y));
        }
    }

#pragma unroll
    for (int r = 0; r < 8; r++) {
        int row = row0 + ty * 8 + r;
        if (row < n_nodes) {
            unsigned c0u, c1u, c2u, c3u;
            asm("mov.b64 {%0, %1}, %2;" : "=r"(c0u), "=r"(c1u) : "l"(acc01[r]));
            asm("mov.b64 {%0, %1}, %2;" : "=r"(c2u), "=r"(c3u) : "l"(acc23[r]));
            float4 xv = ((const float4*)(x + (size_t)row * FEAT))[tx];
            float4 o = make_float4(__uint_as_float(c0u) + xv.x,
                                   __uint_as_float(c1u) + xv.y,
                                   __uint_as_float(c2u) + xv.z,
                                   __uint_as_float(c3u) + xv.w);
            ((float4*)(out + (size_t)row * FEAT))[tx] = o;
        }
    }
}

// ---------------------------------------------------------------------------
extern "C" void kernel_launch(void* const* d_in, const int* in_sizes, int n_in,
                              void* d_out, int out_size) {
    const float* x    = (const float*)d_in[0];
    const int*   ei   = (const int*)d_in[1];
    const float* elen = (const float*)d_in[2];
    const float* W    = (const float*)d_in[3];
    const float* lsc  = (const float*)d_in[4];
    const float* fw   = (const float*)d_in[5];
    const float* fb   = (const float*)d_in[6];
    float* out = (float*)d_out;

    int n_nodes = in_sizes[0] / FEAT;
    int E       = in_sizes[2];
    if (E > MAX_EDGES) E = MAX_EDGES;

    float*  agg;      cudaGetSymbolAddress((void**)&agg, g_agg);
    __half* xh;       cudaGetSymbolAddress((void**)&xh, g_xh);
    int*    deg;      cudaGetSymbolAddress((void**)&deg, g_deg);
    int*    rowstart; cudaGetSymbolAddress((void**)&rowstart, g_rowstart);
    int*    writeptr; cudaGetSymbolAddress((void**)&writeptr, g_writeptr);
    int*    blocksum; cudaGetSymbolAddress((void**)&blocksum, g_blocksum);
    uint2*  rec;      cudaGetSymbolAddress((void**)&rec, g_rec);

    // 0+1) convert x -> fp16 and zero degree counters
    {
        int n8 = n_nodes * FEAT / 8;
        prep_kernel<<<(n8 + 255) / 256, 256>>>(x, xh, deg, n8, n_nodes);
    }

    // 2) receiver histogram
    hist_kernel<<<(E + 255) / 256, 256>>>(ei, deg, E, n_nodes);

    // 3) decoupled prefix scan -> rowstart / writeptr
    {
        int nb = (n_nodes + SCAN_BLK - 1) / SCAN_BLK;   // 196
        scan_reduce_kernel<<<nb, SCAN_BLK>>>(deg, blocksum, n_nodes);
        scan_top_kernel<<<1, SCAN_BLK>>>(blocksum, nb);
        scan_final_kernel<<<nb, SCAN_BLK>>>(deg, blocksum, rowstart,
                                            writeptr, n_nodes);
    }

    // 4) bucket scatter, 4 contiguous edges per thread
    {
        int T = (E + 3) / 4;
        scatter_kernel<<<(T + 255) / 256, 256>>>(ei, elen, lsc, fw, fb,
                                                 writeptr, rec, E, n_nodes);
    }

    // 5) race-free per-node gather (warp per node)
    {
        long long total = (long long)n_nodes * 32;
        int blocks = (int)((total + 255) / 256);
        gather_kernel<<<blocks, 256>>>(xh, rec, rowstart, deg, agg, n_nodes);
    }

    // 6) GEMM + residual
    {
        int smem = (FEAT * FEAT + BM * FEAT) * (int)sizeof(float);  // 96 KB
        cudaFuncSetAttribute(gemm_kernel,
                             cudaFuncAttributeMaxDynamicSharedMemorySize, smem);
        gemm_kernel<<<(n_nodes + BM - 1) / BM, 256, smem>>>(x, W, agg, out,
                                                            n_nodes);
    }
}

// round 11
// speedup vs baseline: 1.7122x; 1.3370x over previous
#include <cuda_runtime.h>
#include <cuda_fp16.h>
#include <math.h>

#define MAX_NODES 50000
#define MAX_EDGES 1500000
#define FEAT 128
#define SCAN_BLK 256
#define MAX_SCAN_BLOCKS 256   // ceil(50000/256)=196

// Scratch (device globals; allocation-free rule)
__device__ __half g_aggh[MAX_NODES * FEAT];   // fp16 normalized aggregate
__device__ __half g_xh[MAX_NODES * FEAT];     // fp16 copy of x
__device__ __half g_wt[FEAT * FEAT];          // fp16 W^T  (wt[n][k] = W[k][n])
__device__ int    g_deg[MAX_NODES];
__device__ int    g_rowstart[MAX_NODES];
__device__ int    g_writeptr[MAX_NODES];
__device__ int    g_blocksum[MAX_SCAN_BLOCKS];
__device__ uint2  g_rec[MAX_EDGES];           // {sender, weight-bits}

// ---------------------------------------------------------------------------
// 0) prep: x -> fp16, W -> fp16 transpose, zero degree counters (one launch)
// ---------------------------------------------------------------------------
__global__ void prep_kernel(const float* __restrict__ x,
                            const float* __restrict__ W,
                            __half* __restrict__ xh,
                            __half* __restrict__ wt,
                            int* __restrict__ deg, int n8, int n_nodes) {
    int i = blockIdx.x * blockDim.x + threadIdx.x;
    if (i < n_nodes) deg[i] = 0;
    if (i < FEAT * FEAT) {
        int n = i / FEAT, k = i % FEAT;
        wt[n * FEAT + k] = __float2half(W[k * FEAT + n]);
    }
    if (i >= n8) return;
    const float4* x4 = (const float4*)x;
    float4 a = x4[2 * i];
    float4 b = x4[2 * i + 1];
    __half2 h0 = __floats2half2_rn(a.x, a.y);
    __half2 h1 = __floats2half2_rn(a.z, a.w);
    __half2 h2 = __floats2half2_rn(b.x, b.y);
    __half2 h3 = __floats2half2_rn(b.z, b.w);
    uint4 o;
    o.x = *(unsigned*)&h0; o.y = *(unsigned*)&h1;
    o.z = *(unsigned*)&h2; o.w = *(unsigned*)&h3;
    ((uint4*)xh)[i] = o;
}

// ---------------------------------------------------------------------------
// 2) histogram of receivers
// ---------------------------------------------------------------------------
__global__ void hist_kernel(const int* __restrict__ ei, int* __restrict__ deg,
                            int E, int n_nodes) {
    int e = blockIdx.x * blockDim.x + threadIdx.x;
    if (e >= E) return;
    int r = ei[E + e];
    r = min(max(r, 0), n_nodes - 1);
    atomicAdd(deg + r, 1);           // no return use -> REDG
}

// ---------------------------------------------------------------------------
// 3) decoupled scan (all shfls with full-warp activity)
// ---------------------------------------------------------------------------
__device__ __forceinline__ int warp_incl_scan(int v, int lane) {
#pragma unroll
    for (int off = 1; off < 32; off <<= 1) {
        int u = __shfl_up_sync(0xffffffffu, v, off);
        if (lane >= off) v += u;
    }
    return v;
}

__global__ void scan_reduce_kernel(const int* __restrict__ deg,
                                   int* __restrict__ blocksum, int n) {
    __shared__ int warpsum[SCAN_BLK / 32];
    int t = threadIdx.x;
    int idx = blockIdx.x * SCAN_BLK + t;
    int v = (idx < n) ? deg[idx] : 0;
#pragma unroll
    for (int off = 16; off > 0; off >>= 1)
        v += __shfl_down_sync(0xffffffffu, v, off);
    if ((t & 31) == 0) warpsum[t >> 5] = v;
    __syncthreads();
    if (t < 32) {
        int s = (t < SCAN_BLK / 32) ? warpsum[t] : 0;
#pragma unroll
        for (int off = 16; off > 0; off >>= 1)
            s += __shfl_down_sync(0xffffffffu, s, off);
        if (t == 0) blocksum[blockIdx.x] = s;
    }
}

__global__ void scan_top_kernel(int* __restrict__ blocksum, int nb) {
    __shared__ int sh[SCAN_BLK / 32];
    int t = threadIdx.x;
    int lane = t & 31;
    int w = t >> 5;
    int v = (t < nb) ? blocksum[t] : 0;
    int incl = warp_incl_scan(v, lane);
    if (lane == 31) sh[w] = incl;
    __syncthreads();
    if (t < 32) {
        int s = (t < SCAN_BLK / 32) ? sh[t] : 0;
        int si = warp_incl_scan(s, t);
        if (t < SCAN_BLK / 32) sh[t] = si - s;
    }
    __syncthreads();
    if (t < nb) blocksum[t] = incl - v + sh[w];
}

__global__ void scan_final_kernel(const int* __restrict__ deg,
                                  const int* __restrict__ blocksum,
                                  int* __restrict__ rowstart,
                                  int* __restrict__ writeptr, int n) {
    __shared__ int sh[SCAN_BLK / 32];
    int t = threadIdx.x;
    int lane = t & 31;
    int w = t >> 5;
    int idx = blockIdx.x * SCAN_BLK + t;
    int v = (idx < n) ? deg[idx] : 0;
    int incl = warp_incl_scan(v, lane);
    if (lane == 31) sh[w] = incl;
    __syncthreads();
    if (t < 32) {
        int s = (t < SCAN_BLK / 32) ? sh[t] : 0;
        int si = warp_incl_scan(s, t);
        if (t < SCAN_BLK / 32) sh[t] = si - s;
    }
    __syncthreads();
    if (idx < n) {
        int start = blocksum[blockIdx.x] + sh[w] + incl - v;
        rowstart[idx] = start;
        writeptr[idx] = start;
    }
}

// ---------------------------------------------------------------------------
// 4) scatter: thread t owns CONTIGUOUS edges 4t..4t+3, vector loads,
//    4 in-flight atomic returns.
// ---------------------------------------------------------------------------
__global__ void scatter_kernel(const int* __restrict__ ei,
                               const float* __restrict__ elen,
                               const float* __restrict__ log_scale_p,
                               const float* __restrict__ fw_p,
                               const float* __restrict__ fb_p,
                               int* __restrict__ writeptr,
                               uint2* __restrict__ rec,
                               int E, int n_nodes) {
    int t = blockIdx.x * blockDim.x + threadIdx.x;
    int e0 = t * 4;
    if (e0 >= E) return;

    float scale = expf(log_scale_p[0]);
    float inv_s = 1.f / (scale + 1e-6f);
    float fw = fw_p[0];
    float fb = fb_p[0];

    int   s[4], r[4];
    float len[4];
    int   cnt;
    if (e0 + 4 <= E && (E & 3) == 0) {
        int4   sv = *(const int4*)(ei + e0);
        int4   rv = *(const int4*)(ei + E + e0);
        float4 lv = *(const float4*)(elen + e0);
        s[0] = sv.x; s[1] = sv.y; s[2] = sv.z; s[3] = sv.w;
        r[0] = rv.x; r[1] = rv.y; r[2] = rv.z; r[3] = rv.w;
        len[0] = lv.x; len[1] = lv.y; len[2] = lv.z; len[3] = lv.w;
        cnt = 4;
    } else {
        cnt = min(4, E - e0);
        for (int u = 0; u < cnt; u++) {
            s[u]   = ei[e0 + u];
            r[u]   = ei[E + e0 + u];
            len[u] = elen[e0 + u];
        }
    }

    float w[4];
    int   pos[4];
#pragma unroll
    for (int u = 0; u < 4; u++) {
        if (u < cnt) {
            s[u] = min(max(s[u], 0), n_nodes - 1);
            r[u] = min(max(r[u], 0), n_nodes - 1);
            float tt = fmaxf(len[u] * inv_s, 0.f);
            float d = expf(-tt * tt);
            float g = 1.f / (1.f + expf(-(len[u] * fw + fb)));
            float ww = d * g;
            if (!(ww > -3.0e38f && ww < 3.0e38f)) ww = 0.f;
            w[u] = ww;
        }
    }
#pragma unroll
    for (int u = 0; u < 4; u++) {
        if (u < cnt) pos[u] = atomicAdd(writeptr + r[u], 1);
    }
#pragma unroll
    for (int u = 0; u < 4; u++) {
        if (u < cnt) rec[pos[u]] = make_uint2((unsigned)s[u],
                                              __float_as_uint(w[u]));
    }
}

// ---------------------------------------------------------------------------
// 5) gather (fp16 x): warp per node, uniform 8-wide blocks, fp32 accumulate,
//    writes NORMALIZED agg as fp16 (feeds the MMA GEMM).
// ---------------------------------------------------------------------------
__global__ void gather_kernel(const __half* __restrict__ xh,
                              const uint2* __restrict__ rec,
                              const int* __restrict__ rowstart,
                              const int* __restrict__ deg,
                              __half* __restrict__ aggh, int n_nodes) {
    int wid  = (blockIdx.x * blockDim.x + threadIdx.x) >> 5;
    int lane = threadIdx.x & 31;
    if (wid >= n_nodes) return;

    int base = rowstart[wid];
    int d    = deg[wid];
    float4 acc = make_float4(0.f, 0.f, 0.f, 0.f);

    for (int j0 = 0; j0 < d; j0 += 32) {
        int n = min(32, d - j0);
        uint2 rv = make_uint2(0u, 0u);
        if (lane < n) rv = rec[base + j0 + lane];

        for (int k = 0; k < n; k += 8) {
            int   si[8];
            float wi[8];
#pragma unroll
            for (int u = 0; u < 8; u++) {
                si[u] = __shfl_sync(0xffffffffu, (int)rv.x, k + u);
                wi[u] = __uint_as_float(__shfl_sync(0xffffffffu, rv.y, k + u));
            }
            uint2 hv[8];
#pragma unroll
            for (int u = 0; u < 8; u++) {
                hv[u] = ((const uint2*)(xh + (size_t)si[u] * FEAT))[lane];
            }
#pragma unroll
            for (int u = 0; u < 8; u++) {
                float2 f0 = __half22float2(*(__half2*)&hv[u].x);
                float2 f1 = __half22float2(*(__half2*)&hv[u].y);
                acc.x = fmaf(wi[u], f0.x, acc.x);
                acc.y = fmaf(wi[u], f0.y, acc.y);
                acc.z = fmaf(wi[u], f1.x, acc.z);
                acc.w = fmaf(wi[u], f1.y, acc.w);
            }
        }
    }

    float inv = 1.f / fmaxf((float)d, 1.f);
    __half2 h0 = __floats2half2_rn(acc.x * inv, acc.y * inv);
    __half2 h1 = __floats2half2_rn(acc.z * inv, acc.w * inv);
    uint2 o;
    o.x = *(unsigned*)&h0; o.y = *(unsigned*)&h1;
    ((uint2*)(aggh + (size_t)wid * FEAT))[lane] = o;
}

// ---------------------------------------------------------------------------
// 6) out = x + aggh @ W  via mma.sync.m16n8k16 (f16 in, f32 accum)
//    CTA: 128 rows x 128 cols, 8 warps (16 rows each).
//    smem: A tile (128 x 128 fp16) + Wt (128 x 128 fp16), pitch 136 halves
//    (272 B) for conflict-free ldmatrix.
// ---------------------------------------------------------------------------
#define GM 128
#define PITCH 136   // halves; 272 B, multiple of 16 B

__global__ void gemm_kernel(const float* __restrict__ x,
                            const __half* __restrict__ wt,
                            const __half* __restrict__ aggh,
                            float* __restrict__ out,
                            int n_nodes) {
    extern __shared__ __half sh[];
    __half* sA = sh;                  // GM rows * PITCH
    __half* sB = sh + GM * PITCH;     // FEAT rows * PITCH (Wt: [n][k])

    int tid = threadIdx.x;
    int lane = tid & 31;
    int wid = tid >> 5;               // 0..7
    int row0 = blockIdx.x * GM;

    // stage A (zero-pad rows >= n_nodes) and Wt; 16 uint4 per row
    for (int i = tid; i < GM * 16; i += 256) {
        int r = i >> 4;
        int c = i & 15;
        uint4 v = make_uint4(0u, 0u, 0u, 0u);
        int row = row0 + r;
        if (row < n_nodes) {
            v = ((const uint4*)(aggh + (size_t)row * FEAT))[c];
        }
        *(uint4*)(sA + r * PITCH + c * 8) = v;
    }
    for (int i = tid; i < FEAT * 16; i += 256) {
        int r = i >> 4;
        int c = i & 15;
        uint4 v = ((const uint4*)(wt + r * FEAT))[c];
        *(uint4*)(sB + r * PITCH + c * 8) = v;
    }
    __syncthreads();

    int warpRow = wid * 16;
    int g = lane >> 2;        // 0..7
    int tg = lane & 3;        // 0..3

    // preload all 8 A k-frags: ldmatrix.x4 each
    unsigned af[8][4];
    {
        int arow = warpRow + (lane & 15);
        int acolH = (lane >> 4) << 3;   // 0 or 8 halves
#pragma unroll
        for (int kk = 0; kk < 8; kk++) {
            unsigned addr = (unsigned)__cvta_generic_to_shared(
                sA + arow * PITCH + kk * 16 + acolH);
            asm volatile(
                "ldmatrix.sync.aligned.m8n8.x4.shared.b16 {%0,%1,%2,%3}, [%4];"
                : "=r"(af[kk][0]), "=r"(af[kk][1]),
                  "=r"(af[kk][2]), "=r"(af[kk][3])
                : "r"(addr));
        }
    }

    int r1 = row0 + warpRow + g;
    int r2 = r1 + 8;

    // n-tiles two at a time for ILP
#pragma unroll
    for (int n = 0; n < 16; n += 2) {
        float c0[4] = {0.f, 0.f, 0.f, 0.f};
        float c1[4] = {0.f, 0.f, 0.f, 0.f};
#pragma unroll
        for (int kk = 0; kk < 8; kk++) {
            // B frag (n): matrix0 lanes0-7 rows n*8..+7 col kk*16;
            //             matrix1 lanes8-15 same rows col kk*16+8
            int brow0 = (n << 3) + (lane & 7);
            int bcol  = (kk << 4) + (((lane >> 3) & 1) << 3);
            unsigned baddr0 = (unsigned)__cvta_generic_to_shared(
                sB + brow0 * PITCH + bcol);
            unsigned baddr1 = (unsigned)__cvta_generic_to_shared(
                sB + (brow0 + 8) * PITCH + bcol);
            unsigned b0, b1, b2, b3;
            asm volatile(
                "ldmatrix.sync.aligned.m8n8.x2.shared.b16 {%0,%1}, [%2];"
                : "=r"(b0), "=r"(b1) : "r"(baddr0));
            asm volatile(
                "ldmatrix.sync.aligned.m8n8.x2.shared.b16 {%0,%1}, [%2];"
                : "=r"(b2), "=r"(b3) : "r"(baddr1));
            asm volatile(
                "mma.sync.aligned.m16n8k16.row.col.f32.f16.f16.f32 "
                "{%0,%1,%2,%3}, {%4,%5,%6,%7}, {%8,%9}, {%0,%1,%2,%3};"
                : "+f"(c0[0]), "+f"(c0[1]), "+f"(c0[2]), "+f"(c0[3])
                : "r"(af[kk][0]), "r"(af[kk][1]), "r"(af[kk][2]), "r"(af[kk][3]),
                  "r"(b0), "r"(b1));
            asm volatile(
                "mma.sync.aligned.m16n8k16.row.col.f32.f16.f16.f32 "
                "{%0,%1,%2,%3}, {%4,%5,%6,%7}, {%8,%9}, {%0,%1,%2,%3};"
                : "+f"(c1[0]), "+f"(c1[1]), "+f"(c1[2]), "+f"(c1[3])
                : "r"(af[kk][0]), "r"(af[kk][1]), "r"(af[kk][2]), "r"(af[kk][3]),
                  "r"(b2), "r"(b3));
        }
        // epilogue: cols for tile n: n*8 + 2*tg, tile n+1: (n+1)*8 + 2*tg
        int col0 = (n << 3) + (tg << 1);
        int col1 = col0 + 8;
        if (r1 < n_nodes) {
            float2 xv0 = *(const float2*)(x + (size_t)r1 * FEAT + col0);
            float2 xv1 = *(const float2*)(x + (size_t)r1 * FEAT + col1);
            *(float2*)(out + (size_t)r1 * FEAT + col0) =
                make_float2(c0[0] + xv0.x, c0[1] + xv0.y);
            *(float2*)(out + (size_t)r1 * FEAT + col1) =
                make_float2(c1[0] + xv1.x, c1[1] + xv1.y);
        }
        if (r2 < n_nodes) {
            float2 xv0 = *(const float2*)(x + (size_t)r2 * FEAT + col0);
            float2 xv1 = *(const float2*)(x + (size_t)r2 * FEAT + col1);
            *(float2*)(out + (size_t)r2 * FEAT + col0) =
                make_float2(c0[2] + xv0.x, c0[3] + xv0.y);
            *(float2*)(out + (size_t)r2 * FEAT + col1) =
                make_float2(c1[2] + xv1.x, c1[3] + xv1.y);
        }
    }
}

// ---------------------------------------------------------------------------
extern "C" void kernel_launch(void* const* d_in, const int* in_sizes, int n_in,
                              void* d_out, int out_size) {
    const float* x    = (const float*)d_in[0];
    const int*   ei   = (const int*)d_in[1];
    const float* elen = (const float*)d_in[2];
    const float* W    = (const float*)d_in[3];
    const float* lsc  = (const float*)d_in[4];
    const float* fw   = (const float*)d_in[5];
    const float* fb   = (const float*)d_in[6];
    float* out = (float*)d_out;

    int n_nodes = in_sizes[0] / FEAT;
    int E       = in_sizes[2];
    if (E > MAX_EDGES) E = MAX_EDGES;

    __half* aggh;     cudaGetSymbolAddress((void**)&aggh, g_aggh);
    __half* xh;       cudaGetSymbolAddress((void**)&xh, g_xh);
    __half* wt;       cudaGetSymbolAddress((void**)&wt, g_wt);
    int*    deg;      cudaGetSymbolAddress((void**)&deg, g_deg);
    int*    rowstart; cudaGetSymbolAddress((void**)&rowstart, g_rowstart);
    int*    writeptr; cudaGetSymbolAddress((void**)&writeptr, g_writeptr);
    int*    blocksum; cudaGetSymbolAddress((void**)&blocksum, g_blocksum);
    uint2*  rec;      cudaGetSymbolAddress((void**)&rec, g_rec);

    // 0+1) convert x -> fp16, W -> Wt fp16, zero degree counters
    {
        int n8 = n_nodes * FEAT / 8;
        prep_kernel<<<(n8 + 255) / 256, 256>>>(x, W, xh, wt, deg, n8, n_nodes);
    }

    // 2) receiver histogram
    hist_kernel<<<(E + 255) / 256, 256>>>(ei, deg, E, n_nodes);

    // 3) decoupled prefix scan -> rowstart / writeptr
    {
        int nb = (n_nodes + SCAN_BLK - 1) / SCAN_BLK;   // 196
        scan_reduce_kernel<<<nb, SCAN_BLK>>>(deg, blocksum, n_nodes);
        scan_top_kernel<<<1, SCAN_BLK>>>(blocksum, nb);
        scan_final_kernel<<<nb, SCAN_BLK>>>(deg, blocksum, rowstart,
                                            writeptr, n_nodes);
    }

    // 4) bucket scatter, 4 contiguous edges per thread
    {
        int T = (E + 3) / 4;
        scatter_kernel<<<(T + 255) / 256, 256>>>(ei, elen, lsc, fw, fb,
                                                 writeptr, rec, E, n_nodes);
    }

    // 5) race-free per-node gather (warp per node) -> fp16 agg
    {
        long long total = (long long)n_nodes * 32;
        int blocks = (int)((total + 255) / 256);
        gather_kernel<<<blocks, 256>>>(xh, rec, rowstart, deg, aggh, n_nodes);
    }

    // 6) tensor-core GEMM + residual
    {
        int smem = (GM * PITCH + FEAT * PITCH) * (int)sizeof(__half); // ~68 KB
        cudaFuncSetAttribute(gemm_kernel,
                             cudaFuncAttributeMaxDynamicSharedMemorySize, smem);
        gemm_kernel<<<(n_nodes + GM - 1) / GM, 256, smem>>>(x, wt, aggh, out,
                                                            n_nodes);
    }
}